// round 17
// baseline (speedup 1.0000x reference)
#include <cuda_runtime.h>

#define NT 128           // threads per block; each thread owns 2 batch rows
#define BTOT 32768
typedef unsigned long long u64;

// ---------------- scratch (allocation-free rule: __device__ globals) --------
static __device__ float g_hq[BTOT * 4];
static __device__ float g_hp[BTOT * 4];

// ---------------- f32x2 helpers ---------------------------------------------
__device__ __forceinline__ u64 splat2(float x) {
    u64 r;
    asm("mov.b64 %0, {%1, %1};" : "=l"(r) : "f"(x));
    return r;
}
__device__ __forceinline__ u64 fma2(u64 a, u64 b, u64 c) {
    u64 d;
    asm("fma.rn.f32x2 %0, %1, %2, %3;" : "=l"(d) : "l"(a), "l"(b), "l"(c));
    return d;
}
__device__ __forceinline__ void unpack2(u64 v, float& lo, float& hi) {
    asm("mov.b64 {%0, %1}, %2;" : "=f"(lo), "=f"(hi) : "l"(v));
}

// ---------------- fast activations (MUFU-based, ~1e-6 accurate) -------------
__device__ __forceinline__ float sigf(float x) {
    return __fdividef(1.0f, 1.0f + __expf(-x));
}
__device__ __forceinline__ float tanhfast(float x) {
    float e = __expf(2.0f * x);
    return 1.0f - __fdividef(2.0f, e + 1.0f);
}

// ---------------- shared-memory layout (floats) -----------------------------
// One tower's weights resident at a time (re-packed per phase), gate-
// interleaved w4[k][j][{i,f,g,o}] exactly as the R7 layout.
static const int OFF_WIH0 = 0;               // 50*25*4 = 5000
static const int OFF_WHH0 = 5000;            // 25*25*4 = 2500
static const int OFF_B0   = 7500;            // 100
static const int OFF_WIH1 = 7600;            // 25*10*4 = 1000
static const int OFF_WHH1 = 8600;            // 10*10*4 = 400
static const int OFF_B1   = 9000;            // 40
static const int OFF_WIH2 = 9040;            // 10*4*4 = 160
static const int OFF_WHH2 = 9200;            // 4*4*4 = 64
static const int OFF_B2   = 9264;            // 16
static const int W_TOTAL  = 9280;
// Per-thread-private float2 {row0,row1} columns (smem as register extension;
// every thread touches ONLY its own column -> no syncs in the main loop).
static const int F_XSTG = W_TOTAL;                 // 50 slots  * NT float2
static const int F_HOLD = F_XSTG + 50 * NT * 2;    // 25 slots  * NT float2
static const int F_H    = F_HOLD + 25 * NT * 2;    // 39 units  * NT float2
static const int F_C    = F_H    + 39 * NT * 2;    // 39 units  * 2*NT float
static const int SMEM_FLOATS = F_C + 39 * 2 * NT;  // 48448
static const int SMEM_BYTES  = SMEM_FLOATS * 4;    // 193,792 B -> 1 block/SM

// ---------------- weight packers --------------------------------------------
// src Wih: [4H, DIN] row-major (torch gate order i,f,g,o).
// dst[(k*H+j)*4+g] = src[(g*H+j)*DIN+k]
template <int DIN, int H>
__device__ void packw(float* dst, const float* __restrict__ src, int tid) {
    const int n = DIN * H * 4;
    for (int idx = tid; idx < n; idx += NT) {
        int g = idx & 3, jk = idx >> 2;
        int j = jk % H, k = jk / H;
        dst[idx] = src[(g * H + j) * DIN + k];
    }
}
template <int H>
__device__ void packb(float* dst, const float* __restrict__ src, int tid) {
    for (int idx = tid; idx < 4 * H; idx += NT) {
        int g = idx & 3, j = idx >> 2;
        dst[idx] = src[g * H + j];
    }
}

// ---------------- one layer step: 2 rows/thread, j-tiled, rolled k-loops ----
// xst/hst/holdst: float2 {r0,r1} columns (+tid applied, stride NT per slot).
// cst: float column (+tid), unit u at cst[u*2*NT] (r0) / +NT (r1).
// One LDS.128 weight load feeds 4 FFMA2 (8 MACs).
template <int DIN, int H, int JB>
__device__ __forceinline__ void step2r(
    const float2* xst,
    const float* wb, int oWih, int oWhh, int oB,
    float2* hst, float2* holdst, float* cst)
{
    // capture h(t-1) into private hold column (epilogue overwrites hst)
#pragma unroll
    for (int k = 0; k < H; k++) holdst[k * NT] = hst[k * NT];

    const ulonglong2* wih = reinterpret_cast<const ulonglong2*>(wb + oWih);
    const ulonglong2* whh = reinterpret_cast<const ulonglong2*>(wb + oWhh);
    const ulonglong2* bb  = reinterpret_cast<const ulonglong2*>(wb + oB);

#pragma unroll 1
    for (int jt = 0; jt < H; jt += JB) {
        u64 aI0[JB], aG0[JB], aI1[JB], aG1[JB];
#pragma unroll
        for (int jj = 0; jj < JB; jj++) {
            ulonglong2 b = bb[jt + jj];
            aI0[jj] = b.x; aG0[jj] = b.y;    // row0: {i,f}, {g,o}
            aI1[jj] = b.x; aG1[jj] = b.y;    // row1
        }
#pragma unroll 2
        for (int k = 0; k < DIN; k++) {
            float2 xv = xst[k * NT];
            u64 x0 = splat2(xv.x);
            u64 x1 = splat2(xv.y);
#pragma unroll
            for (int jj = 0; jj < JB; jj++) {
                ulonglong2 w = wih[k * H + jt + jj];   // one LDS.128 -> 8 MACs
                aI0[jj] = fma2(x0, w.x, aI0[jj]);
                aG0[jj] = fma2(x0, w.y, aG0[jj]);
                aI1[jj] = fma2(x1, w.x, aI1[jj]);
                aG1[jj] = fma2(x1, w.y, aG1[jj]);
            }
        }
#pragma unroll 2
        for (int k = 0; k < H; k++) {
            float2 hv = holdst[k * NT];
            u64 h0 = splat2(hv.x);
            u64 h1 = splat2(hv.y);
#pragma unroll
            for (int jj = 0; jj < JB; jj++) {
                ulonglong2 w = whh[k * H + jt + jj];
                aI0[jj] = fma2(h0, w.x, aI0[jj]);
                aG0[jj] = fma2(h0, w.y, aG0[jj]);
                aI1[jj] = fma2(h1, w.x, aI1[jj]);
                aG1[jj] = fma2(h1, w.y, aG1[jj]);
            }
        }
#pragma unroll
        for (int jj = 0; jj < JB; jj++) {
            int u = jt + jj;
            float ai, af, ag, ao, bi, bf, bg, bo;
            unpack2(aI0[jj], ai, af);
            unpack2(aG0[jj], ag, ao);
            unpack2(aI1[jj], bi, bf);
            unpack2(aG1[jj], bg, bo);
            float c0 = cst[u * 2 * NT];
            float c1 = cst[u * 2 * NT + NT];
            float c0n = fmaf(sigf(af), c0, sigf(ai) * tanhfast(ag));
            float c1n = fmaf(sigf(bf), c1, sigf(bi) * tanhfast(bg));
            cst[u * 2 * NT]      = c0n;
            cst[u * 2 * NT + NT] = c1n;
            hst[u * NT] = make_float2(sigf(ao) * tanhfast(c0n),
                                      sigf(bo) * tanhfast(c1n));
        }
    }
}

// ---------------- uniform dual-phase kernel ----------------------------------
// 128 blocks; each block runs 256 p-rows (T=50) then 256 q-rows (T=12).
// Uniform work -> single wave; weights re-packed per phase.
__global__ void __launch_bounds__(NT, 1)
towers_kernel(
    const float* __restrict__ q, const float* __restrict__ p,
    const float* qa0, const float* qa1, const float* qa2,
    const float* qa3, const float* qa4, const float* qa5,
    const float* qa6, const float* qa7, const float* qa8,
    const float* pa0, const float* pa1, const float* pa2,
    const float* pa3, const float* pa4, const float* pa5,
    const float* pa6, const float* pa7, const float* pa8)
{
    extern __shared__ float sm[];
    const int tid = threadIdx.x;

    float2* xstg  = reinterpret_cast<float2*>(sm + F_XSTG) + tid;
    float2* holds = reinterpret_cast<float2*>(sm + F_HOLD) + tid;
    float2* hb    = reinterpret_cast<float2*>(sm + F_H)    + tid;
    float*  cb    = sm + F_C + tid;

#pragma unroll 1
    for (int phase = 0; phase < 2; phase++) {
        const float* w[9];
        int T;
        const float* xin;
        float* hout;
        if (phase == 0) {
            w[0]=pa0; w[1]=pa1; w[2]=pa2; w[3]=pa3; w[4]=pa4;
            w[5]=pa5; w[6]=pa6; w[7]=pa7; w[8]=pa8;
            T = 50; xin = p; hout = g_hp;
        } else {
            w[0]=qa0; w[1]=qa1; w[2]=qa2; w[3]=qa3; w[4]=qa4;
            w[5]=qa5; w[6]=qa6; w[7]=qa7; w[8]=qa8;
            T = 12; xin = q; hout = g_hq;
        }

        __syncthreads();   // all threads done reading previous phase's weights
        packw<50, 25>(sm + OFF_WIH0, w[0], tid);
        packw<25, 25>(sm + OFF_WHH0, w[1], tid);
        packb<25>(sm + OFF_B0, w[2], tid);
        packw<25, 10>(sm + OFF_WIH1, w[3], tid);
        packw<10, 10>(sm + OFF_WHH1, w[4], tid);
        packb<10>(sm + OFF_B1, w[5], tid);
        packw<10, 4>(sm + OFF_WIH2, w[6], tid);
        packw<4, 4>(sm + OFF_WHH2, w[7], tid);
        packb<4>(sm + OFF_B2, w[8], tid);
        __syncthreads();

        // zero state (own columns only)
#pragma unroll
        for (int u = 0; u < 39; u++) {
            hb[u * NT] = make_float2(0.0f, 0.0f);
            cb[u * 2 * NT] = 0.0f;
            cb[u * 2 * NT + NT] = 0.0f;
        }

        const int base = blockIdx.x * 2 * NT;
        const int r0 = base + tid;
        const int r1 = base + NT + tid;
        const float* xr0 = xin + (size_t)r0 * T * 50;
        const float* xr1 = xin + (size_t)r1 * T * 50;

#pragma unroll 1
        for (int t = 0; t < T; t++) {
            // stage this step's inputs for both rows into private columns
            const float2* xp0 = reinterpret_cast<const float2*>(xr0 + t * 50);
            const float2* xp1 = reinterpret_cast<const float2*>(xr1 + t * 50);
#pragma unroll
            for (int i = 0; i < 25; i++) {
                float2 a = __ldg(xp0 + i);
                float2 b = __ldg(xp1 + i);
                xstg[(2 * i) * NT]     = make_float2(a.x, b.x);
                xstg[(2 * i + 1) * NT] = make_float2(a.y, b.y);
            }
            step2r<50, 25, 5>(xstg, sm, OFF_WIH0, OFF_WHH0, OFF_B0,
                              hb, holds, cb);
            step2r<25, 10, 5>(hb, sm, OFF_WIH1, OFF_WHH1, OFF_B1,
                              hb + 25 * NT, holds, cb + 25 * 2 * NT);
            step2r<10, 4, 4>(hb + 25 * NT, sm, OFF_WIH2, OFF_WHH2, OFF_B2,
                             hb + 35 * NT, holds, cb + 35 * 2 * NT);
        }

#pragma unroll
        for (int j = 0; j < 4; j++) {
            float2 v = hb[(35 + j) * NT];
            hout[r0 * 4 + j] = v.x;
            hout[r1 * 4 + j] = v.y;
        }
    }
}

// ---------------- combine: scores -> softmax --------------------------------
__global__ void __launch_bounds__(256)
combine_kernel(const float* __restrict__ fW, const float* __restrict__ fb,
               float* __restrict__ out)
{
    int row = blockIdx.x * blockDim.x + threadIdx.x;
    float s0 = g_hq[row * 4 + 0] * g_hp[row * 4 + 0];
    float s1 = g_hq[row * 4 + 1] * g_hp[row * 4 + 1];
    float s2 = g_hq[row * 4 + 2] * g_hp[row * 4 + 2];
    float s3 = g_hq[row * 4 + 3] * g_hp[row * 4 + 3];
    float l0 = __ldg(fb + 0) + __ldg(fW + 0) * s0 + __ldg(fW + 1) * s1
                             + __ldg(fW + 2) * s2 + __ldg(fW + 3) * s3;
    float l1 = __ldg(fb + 1) + __ldg(fW + 4) * s0 + __ldg(fW + 5) * s1
                             + __ldg(fW + 6) * s2 + __ldg(fW + 7) * s3;
    float m = fmaxf(l0, l1);
    float e0 = __expf(l0 - m);
    float e1 = __expf(l1 - m);
    float inv = __fdividef(1.0f, e0 + e1);
    out[row * 2 + 0] = e0 * inv;
    out[row * 2 + 1] = e1 * inv;
}

// ---------------- launch ----------------------------------------------------
extern "C" void kernel_launch(void* const* d_in, const int* in_sizes, int n_in,
                              void* d_out, int out_size)
{
    const float* q  = (const float*)d_in[0];
    const float* p  = (const float*)d_in[1];
    const float* qw[9];
    const float* pw[9];
    for (int i = 0; i < 9; i++) qw[i] = (const float*)d_in[2 + i];
    for (int i = 0; i < 9; i++) pw[i] = (const float*)d_in[11 + i];
    const float* fW = (const float*)d_in[20];
    const float* fb = (const float*)d_in[21];
    float* out = (float*)d_out;

    cudaFuncSetAttribute(towers_kernel,
                         cudaFuncAttributeMaxDynamicSharedMemorySize, SMEM_BYTES);

    towers_kernel<<<BTOT / (2 * NT), NT, SMEM_BYTES>>>(
        q, p,
        qw[0], qw[1], qw[2], qw[3], qw[4], qw[5], qw[6], qw[7], qw[8],
        pw[0], pw[1], pw[2], pw[3], pw[4], pw[5], pw[6], pw[7], pw[8]);
    combine_kernel<<<BTOT / 256, 256>>>(fW, fb, out);
}